// round 2
// baseline (speedup 1.0000x reference)
#include <cuda_runtime.h>
#include <stdint.h>

// CubeSpherePadding2D, p=1, input [16,64,6,96,96] f32 -> output [16,64,6,98,98] f32.
//
// The reference does 24 sequential in-place edge assignments. Dependency analysis
// (p=1) shows the final result is a pure gather of the ORIGINAL input:
//   - interior  : direct copy
//   - edge bulk : original data of the neighbor face (with transpose/flip mapping)
//   - corners   : faces 0-3 -> 0 (source edges written later in the sequence);
//                 faces 4,5 -> depth-2 resolved original values.
// Single fully-coalesced gather kernel, graph-capturable.

#define H 96
#define W 96
#define OH 98
#define OW 98
#define FACE (H * W)        // 9216
#define OFACE (OH * OW)     // 9604

__device__ __forceinline__ float Oat(const float* __restrict__ B, int g, int y, int x) {
    return B[g * FACE + y * W + x];
}

__global__ void cube_pad_kernel(const float* __restrict__ in,
                                float* __restrict__ out,
                                int total) {
    int idx = blockIdx.x * blockDim.x + threadIdx.x;
    if (idx >= total) return;

    int slice = idx / OFACE;            // bc * 6 + f
    int rem   = idx - slice * OFACE;
    int r     = rem / OW;
    int c     = rem - r * OW;
    int f     = slice % 6;
    int bc    = slice / 6;

    const float* __restrict__ B = in + (size_t)bc * 6 * FACE;

    bool rin = (unsigned)(r - 1) < 96u;   // 1..96
    bool cin = (unsigned)(c - 1) < 96u;

    float v = 0.0f;

    if (rin && cin) {
        // interior: dominant, coalesced path
        v = Oat(B, f, r - 1, c - 1);
    } else if (cin) {
        // top (r==0) or bottom (r==97) row, non-corner
        bool top = (r == 0);
        switch (f) {
            case 0: v = top ? Oat(B, 4, 95, c - 1)   : Oat(B, 5, 0, c - 1);   break;
            case 1: v = top ? Oat(B, 4, 96 - c, 95)  : Oat(B, 5, c - 1, 95);  break;
            case 2: v = top ? Oat(B, 4, 0, 96 - c)   : Oat(B, 5, 95, 96 - c); break;
            case 3: v = top ? Oat(B, 4, c - 1, 0)    : Oat(B, 5, 96 - c, 0);  break;
            case 4: v = top ? Oat(B, 2, 0, 96 - c)   : Oat(B, 0, 0, c - 1);   break;
            case 5: v = top ? Oat(B, 0, 95, c - 1)   : Oat(B, 2, 95, 96 - c); break;
        }
    } else if (rin) {
        // left (c==0) or right (c==97) column, non-corner
        bool right = (c == 97);
        switch (f) {
            case 0: v = right ? Oat(B, 1, r - 1, 0)  : Oat(B, 3, r - 1, 95);  break;
            case 1: v = right ? Oat(B, 2, r - 1, 0)  : Oat(B, 0, r - 1, 95);  break;
            case 2: v = right ? Oat(B, 3, r - 1, 0)  : Oat(B, 1, r - 1, 95);  break;
            case 3: v = right ? Oat(B, 0, r - 1, 0)  : Oat(B, 2, r - 1, 95);  break;
            case 4: v = right ? Oat(B, 1, 0, 96 - r) : Oat(B, 3, 0, r - 1);   break;
            case 5: v = right ? Oat(B, 1, 95, r - 1) : Oat(B, 3, 95, 96 - r); break;
        }
    } else {
        // corners: faces 0-3 are 0 (source edges not yet written at assignment
        // time in the reference's sequential order); faces 4,5 resolve depth-2.
        if (f == 4) {
            if (r == 0) v = (c == 0) ? Oat(B, 3, 0, 0)   : Oat(B, 1, 0, 95);
            else        v = (c == 0) ? Oat(B, 3, 0, 95)  : Oat(B, 1, 0, 0);
        } else if (f == 5) {
            if (r == 0) v = (c == 0) ? Oat(B, 3, 95, 95) : Oat(B, 1, 95, 0);
            else        v = (c == 0) ? Oat(B, 3, 95, 0)  : Oat(B, 1, 95, 95);
        }
        // faces 0-3: v stays 0
    }

    out[idx] = v;
}

extern "C" void kernel_launch(void* const* d_in, const int* in_sizes, int n_in,
                              void* d_out, int out_size) {
    const float* in = (const float*)d_in[0];
    float* out = (float*)d_out;

    int total = out_size;  // 16*64*6*98*98 = 59,006,976
    int threads = 256;
    int blocks = (total + threads - 1) / threads;
    cube_pad_kernel<<<blocks, threads>>>(in, out, total);
}

// round 3
// speedup vs baseline: 1.8055x; 1.8055x over previous
#include <cuda_runtime.h>
#include <stdint.h>

// CubeSpherePadding2D, p=1: [16,64,6,96,96] f32 -> [16,64,6,98,98] f32.
// Pure gather of the original input (dependency analysis of the 24 sequential
// reference assignments; verified rel_err==0 in round 1).
//
// Round-2 change: 4 output elements per thread. OFACE=9604 is divisible by 4,
// so each float4 group lies within one slice. ~92% of groups are pure interior
// same-row -> 4 consecutive input loads + one STG.128. Edge/row-crossing groups
// fall back to the verified per-element gather.

#define H 96
#define W 96
#define OH 98
#define OW 98
#define FACE (H * W)        // 9216
#define OFACE (OH * OW)     // 9604

__device__ __forceinline__ float Oat(const float* __restrict__ B, int g, int y, int x) {
    return B[g * FACE + y * W + x];
}

// Per-element gather (verified exact in round 1).
__device__ __forceinline__ float slow_val(const float* __restrict__ in,
                                          int slice, int r, int c) {
    int f = slice % 6;
    const float* __restrict__ B = in + (size_t)(slice - f) * FACE;

    bool rin = (unsigned)(r - 1) < 96u;
    bool cin = (unsigned)(c - 1) < 96u;

    float v = 0.0f;
    if (rin && cin) {
        v = Oat(B, f, r - 1, c - 1);
    } else if (cin) {
        bool top = (r == 0);
        switch (f) {
            case 0: v = top ? Oat(B, 4, 95, c - 1)   : Oat(B, 5, 0, c - 1);   break;
            case 1: v = top ? Oat(B, 4, 96 - c, 95)  : Oat(B, 5, c - 1, 95);  break;
            case 2: v = top ? Oat(B, 4, 0, 96 - c)   : Oat(B, 5, 95, 96 - c); break;
            case 3: v = top ? Oat(B, 4, c - 1, 0)    : Oat(B, 5, 96 - c, 0);  break;
            case 4: v = top ? Oat(B, 2, 0, 96 - c)   : Oat(B, 0, 0, c - 1);   break;
            case 5: v = top ? Oat(B, 0, 95, c - 1)   : Oat(B, 2, 95, 96 - c); break;
        }
    } else if (rin) {
        bool right = (c == 97);
        switch (f) {
            case 0: v = right ? Oat(B, 1, r - 1, 0)  : Oat(B, 3, r - 1, 95);  break;
            case 1: v = right ? Oat(B, 2, r - 1, 0)  : Oat(B, 0, r - 1, 95);  break;
            case 2: v = right ? Oat(B, 3, r - 1, 0)  : Oat(B, 1, r - 1, 95);  break;
            case 3: v = right ? Oat(B, 0, r - 1, 0)  : Oat(B, 2, r - 1, 95);  break;
            case 4: v = right ? Oat(B, 1, 0, 96 - r) : Oat(B, 3, 0, r - 1);   break;
            case 5: v = right ? Oat(B, 1, 95, r - 1) : Oat(B, 3, 95, 96 - r); break;
        }
    } else {
        // corners: faces 0-3 read still-zero padding in the reference order;
        // faces 4,5 resolve depth-2 to original data.
        if (f == 4) {
            if (r == 0) v = (c == 0) ? Oat(B, 3, 0, 0)   : Oat(B, 1, 0, 95);
            else        v = (c == 0) ? Oat(B, 3, 0, 95)  : Oat(B, 1, 0, 0);
        } else if (f == 5) {
            if (r == 0) v = (c == 0) ? Oat(B, 3, 95, 95) : Oat(B, 1, 95, 0);
            else        v = (c == 0) ? Oat(B, 3, 95, 0)  : Oat(B, 1, 95, 95);
        }
    }
    return v;
}

__global__ void __launch_bounds__(256)
cube_pad_v4_kernel(const float* __restrict__ in,
                   float4* __restrict__ out,
                   int ngroups) {
    int g = blockIdx.x * blockDim.x + threadIdx.x;
    if (g >= ngroups) return;

    int idx0  = g * 4;
    int slice = idx0 / OFACE;           // never crosses: OFACE % 4 == 0
    int rem   = idx0 - slice * OFACE;
    int r     = rem / OW;
    int c     = rem - r * OW;

    float4 v;
    if ((unsigned)(r - 1) < 96u && (unsigned)(c - 1) < 93u) {
        // interior, same row, all 4 cols in 1..96: consecutive input gather
        const float* __restrict__ p =
            in + (size_t)slice * FACE + (r - 1) * W + (c - 1);
        v.x = p[0];
        v.y = p[1];
        v.z = p[2];
        v.w = p[3];
    } else {
        int rr = r, cc = c;
        v.x = slow_val(in, slice, rr, cc); if (++cc == OW) { cc = 0; ++rr; }
        v.y = slow_val(in, slice, rr, cc); if (++cc == OW) { cc = 0; ++rr; }
        v.z = slow_val(in, slice, rr, cc); if (++cc == OW) { cc = 0; ++rr; }
        v.w = slow_val(in, slice, rr, cc);
    }

    out[g] = v;
}

extern "C" void kernel_launch(void* const* d_in, const int* in_sizes, int n_in,
                              void* d_out, int out_size) {
    const float* in = (const float*)d_in[0];
    float4* out = (float4*)d_out;

    int ngroups = out_size / 4;         // 59,006,976 / 4 = 14,751,744
    int threads = 256;
    int blocks = (ngroups + threads - 1) / threads;
    cube_pad_v4_kernel<<<blocks, threads>>>(in, out, ngroups);
}

// round 4
// speedup vs baseline: 1.8233x; 1.0098x over previous
#include <cuda_runtime.h>
#include <stdint.h>

// CubeSpherePadding2D, p=1: [16,64,6,96,96] f32 -> [16,64,6,98,98] f32.
// Pure gather of the original input (dependency analysis of the 24 sequential
// reference assignments; rel_err==0 verified in rounds 1-2).
//
// Round-3: 8 outputs per thread (2x float4 stores), 8 independent scalar loads
// on the fast path (MLP=8), index decomposition amortized 8x.

#define H 96
#define W 96
#define OH 98
#define OW 98
#define FACE (H * W)        // 9216
#define OFACE (OH * OW)     // 9604

__device__ __forceinline__ float Oat(const float* __restrict__ B, int g, int y, int x) {
    return B[g * FACE + y * W + x];
}

// Per-element gather from a global output index (verified exact).
__device__ __forceinline__ float slow_val_g(const float* __restrict__ in, int gidx) {
    int slice = gidx / OFACE;
    int rem   = gidx - slice * OFACE;
    int r     = rem / OW;
    int c     = rem - r * OW;
    int f     = slice % 6;
    const float* __restrict__ B = in + (size_t)(slice - f) * FACE;

    bool rin = (unsigned)(r - 1) < 96u;
    bool cin = (unsigned)(c - 1) < 96u;

    float v = 0.0f;
    if (rin && cin) {
        v = Oat(B, f, r - 1, c - 1);
    } else if (cin) {
        bool top = (r == 0);
        switch (f) {
            case 0: v = top ? Oat(B, 4, 95, c - 1)   : Oat(B, 5, 0, c - 1);   break;
            case 1: v = top ? Oat(B, 4, 96 - c, 95)  : Oat(B, 5, c - 1, 95);  break;
            case 2: v = top ? Oat(B, 4, 0, 96 - c)   : Oat(B, 5, 95, 96 - c); break;
            case 3: v = top ? Oat(B, 4, c - 1, 0)    : Oat(B, 5, 96 - c, 0);  break;
            case 4: v = top ? Oat(B, 2, 0, 96 - c)   : Oat(B, 0, 0, c - 1);   break;
            case 5: v = top ? Oat(B, 0, 95, c - 1)   : Oat(B, 2, 95, 96 - c); break;
        }
    } else if (rin) {
        bool right = (c == 97);
        switch (f) {
            case 0: v = right ? Oat(B, 1, r - 1, 0)  : Oat(B, 3, r - 1, 95);  break;
            case 1: v = right ? Oat(B, 2, r - 1, 0)  : Oat(B, 0, r - 1, 95);  break;
            case 2: v = right ? Oat(B, 3, r - 1, 0)  : Oat(B, 1, r - 1, 95);  break;
            case 3: v = right ? Oat(B, 0, r - 1, 0)  : Oat(B, 2, r - 1, 95);  break;
            case 4: v = right ? Oat(B, 1, 0, 96 - r) : Oat(B, 3, 0, r - 1);   break;
            case 5: v = right ? Oat(B, 1, 95, r - 1) : Oat(B, 3, 95, 96 - r); break;
        }
    } else {
        // corners: faces 0-3 read still-zero padding in the reference order;
        // faces 4,5 resolve depth-2 to original data.
        if (f == 4) {
            if (r == 0) v = (c == 0) ? Oat(B, 3, 0, 0)   : Oat(B, 1, 0, 95);
            else        v = (c == 0) ? Oat(B, 3, 0, 95)  : Oat(B, 1, 0, 0);
        } else if (f == 5) {
            if (r == 0) v = (c == 0) ? Oat(B, 3, 95, 95) : Oat(B, 1, 95, 0);
            else        v = (c == 0) ? Oat(B, 3, 95, 0)  : Oat(B, 1, 95, 95);
        }
    }
    return v;
}

__global__ void __launch_bounds__(256)
cube_pad_v8_kernel(const float* __restrict__ in,
                   float4* __restrict__ out,
                   int nthreads) {
    int t = blockIdx.x * blockDim.x + threadIdx.x;
    if (t >= nthreads) return;

    int idx0  = t * 8;
    int slice = idx0 / OFACE;
    int rem   = idx0 - slice * OFACE;
    int r     = rem / OW;
    int c     = rem - r * OW;

    float4 v0, v1;
    if ((unsigned)(r - 1) < 96u && (unsigned)(c - 1) < 89u) {
        // window [c, c+7] fully interior, same row: 8 consecutive input loads
        const float* __restrict__ p =
            in + (size_t)slice * FACE + (r - 1) * W + (c - 1);
        float a0 = p[0], a1 = p[1], a2 = p[2], a3 = p[3];
        float a4 = p[4], a5 = p[5], a6 = p[6], a7 = p[7];
        v0 = make_float4(a0, a1, a2, a3);
        v1 = make_float4(a4, a5, a6, a7);
    } else {
        // edge / row-wrap / slice-wrap: per-element gather from global index
        v0.x = slow_val_g(in, idx0 + 0);
        v0.y = slow_val_g(in, idx0 + 1);
        v0.z = slow_val_g(in, idx0 + 2);
        v0.w = slow_val_g(in, idx0 + 3);
        v1.x = slow_val_g(in, idx0 + 4);
        v1.y = slow_val_g(in, idx0 + 5);
        v1.z = slow_val_g(in, idx0 + 6);
        v1.w = slow_val_g(in, idx0 + 7);
    }

    out[t * 2]     = v0;
    out[t * 2 + 1] = v1;
}

extern "C" void kernel_launch(void* const* d_in, const int* in_sizes, int n_in,
                              void* d_out, int out_size) {
    const float* in = (const float*)d_in[0];
    float4* out = (float4*)d_out;

    // out_size = 59,006,976 = 8 * 7,375,872 (divisible by 8)
    int nthreads = out_size / 8;
    int threads = 256;
    int blocks = (nthreads + threads - 1) / threads;
    cube_pad_v8_kernel<<<blocks, threads>>>(in, out, nthreads);
}

// round 7
// speedup vs baseline: 2.3906x; 1.3111x over previous
#include <cuda_runtime.h>
#include <stdint.h>

// CubeSpherePadding2D, p=1: [16,64,6,96,96] f32 -> [16,64,6,98,98] f32.
// Pure gather of the original input (reference's 24 sequential edge writes
// resolved analytically; rel_err==0 verified rounds 1-3).
//
// Round-4 layout: each thread handles 8 elements at the SAME (r,c) position in
// 8 slices strided 768 apart (768 % 6 == 0 -> same face, same edge case).
// Consecutive lanes -> consecutive c -> every LDG.32/STG.32 is a contiguous
// 128B warp access (1 L1 wavefront; v8 had 8x amplification on loads).

#define H 96
#define W 96
#define OH 98
#define OW 98
#define FACE (H * W)        // 9216
#define OFACE (OH * OW)     // 9604
#define NSL_GRP 768         // slice stride between a thread's elements
#define NJ 8                // elements per thread

__device__ __forceinline__ int src_off(int g, int y, int x) {
    return g * FACE + y * W + x;
}

// Source offset within the thread's 6-face block for an edge/corner output
// position (f, r, c). Returns -1 for the zero corners (faces 0-3).
__device__ __forceinline__ int edge_src_offset(int f, int r, int c) {
    bool rin = (unsigned)(r - 1) < 96u;
    bool cin = (unsigned)(c - 1) < 96u;

    if (rin && cin) {                       // interior (not used on fallback, safe)
        return src_off(f, r - 1, c - 1);
    }
    if (cin) {                              // top/bottom row, non-corner
        bool top = (r == 0);
        switch (f) {
            case 0: return top ? src_off(4, 95, c - 1)   : src_off(5, 0, c - 1);
            case 1: return top ? src_off(4, 96 - c, 95)  : src_off(5, c - 1, 95);
            case 2: return top ? src_off(4, 0, 96 - c)   : src_off(5, 95, 96 - c);
            case 3: return top ? src_off(4, c - 1, 0)    : src_off(5, 96 - c, 0);
            case 4: return top ? src_off(2, 0, 96 - c)   : src_off(0, 0, c - 1);
            default:return top ? src_off(0, 95, c - 1)   : src_off(2, 95, 96 - c);
        }
    }
    if (rin) {                              // left/right column, non-corner
        bool right = (c == 97);
        switch (f) {
            case 0: return right ? src_off(1, r - 1, 0)  : src_off(3, r - 1, 95);
            case 1: return right ? src_off(2, r - 1, 0)  : src_off(0, r - 1, 95);
            case 2: return right ? src_off(3, r - 1, 0)  : src_off(1, r - 1, 95);
            case 3: return right ? src_off(0, r - 1, 0)  : src_off(2, r - 1, 95);
            case 4: return right ? src_off(1, 0, 96 - r) : src_off(3, 0, r - 1);
            default:return right ? src_off(1, 95, r - 1) : src_off(3, 95, 96 - r);
        }
    }
    // corners: faces 0-3 read still-zero padding (reference assignment order);
    // faces 4,5 resolve depth-2 to original data.
    if (f == 4) {
        if (r == 0) return (c == 0) ? src_off(3, 0, 0)   : src_off(1, 0, 95);
        else        return (c == 0) ? src_off(3, 0, 95)  : src_off(1, 0, 0);
    }
    if (f == 5) {
        if (r == 0) return (c == 0) ? src_off(3, 95, 95) : src_off(1, 95, 0);
        else        return (c == 0) ? src_off(3, 95, 0)  : src_off(1, 95, 95);
    }
    return -1;
}

__global__ void __launch_bounds__(256)
cube_pad_sstride_kernel(const float* __restrict__ in,
                        float* __restrict__ out,
                        int nthreads) {
    int t = blockIdx.x * blockDim.x + threadIdx.x;
    if (t >= nthreads) return;

    // Decompose within the first 768-slice block; elements j advance by
    // NSL_GRP slices (same face, same (r,c), same edge case).
    int slice0 = t / OFACE;             // 0..767
    int rem    = t - slice0 * OFACE;
    int r      = rem / OW;
    int c      = rem - r * OW;

    const long long S_IN  = (long long)NSL_GRP * FACE;    // 7,077,888
    const long long S_OUT = (long long)NSL_GRP * OFACE;   // 7,375,872

    float* __restrict__ op = out + (long long)slice0 * OFACE + r * OW + c;

    if ((unsigned)(r - 1) < 96u && (unsigned)(c - 1) < 96u) {
        // Interior: direct copy, lanes contiguous in c on both sides.
        const float* __restrict__ ip =
            in + (long long)slice0 * FACE + (r - 1) * W + (c - 1);
        float v[NJ];
        #pragma unroll
        for (int j = 0; j < NJ; ++j) v[j] = __ldg(ip + j * S_IN);
        #pragma unroll
        for (int j = 0; j < NJ; ++j) op[j * S_OUT] = v[j];
    } else {
        // Edge/corner: classify ONCE, apply to all 8 slices.
        int f   = slice0 % 6;
        int off = edge_src_offset(f, r, c);
        const float* __restrict__ B0 = in + (long long)(slice0 - f) * FACE;
        if (off >= 0) {
            float v[NJ];
            #pragma unroll
            for (int j = 0; j < NJ; ++j) v[j] = __ldg(B0 + off + j * S_IN);
            #pragma unroll
            for (int j = 0; j < NJ; ++j) op[j * S_OUT] = v[j];
        } else {
            #pragma unroll
            for (int j = 0; j < NJ; ++j) op[j * S_OUT] = 0.0f;
        }
    }
}

extern "C" void kernel_launch(void* const* d_in, const int* in_sizes, int n_in,
                              void* d_out, int out_size) {
    const float* in = (const float*)d_in[0];
    float* out = (float*)d_out;

    // out_size = 59,006,976 = 8 * 768 * 9604
    int nthreads = out_size / NJ;       // 7,375,872
    int threads = 256;
    int blocks = (nthreads + threads - 1) / threads;
    cube_pad_sstride_kernel<<<blocks, threads>>>(in, out, nthreads);
}